// round 4
// baseline (speedup 1.0000x reference)
#include <cuda_runtime.h>
#include <cstdint>

#define BB   64
#define TT   1024
#define IND  7
#define EE   64
#define HH   2
#define DHH  32
#define QKV3 192
#define ROWS (BB*TT)

#define ATTN_SCALE 0.17677669529663687f  // 1/sqrt(32)

// cp.async 16B: global -> shared, L2-only cache policy (.cg)
#define CP_ASYNC16(dst_u32, src_ptr) \
    asm volatile("cp.async.cg.shared.global [%0], [%1], 16;" :: "r"(dst_u32), "l"(src_ptr) : "memory")
#define CP_COMMIT()   asm volatile("cp.async.commit_group;" ::: "memory")
#define CP_WAIT(N)    asm volatile("cp.async.wait_group %0;" :: "n"(N) : "memory")

// ---------- scratch (device globals; no allocation allowed) ----------
__device__ float g_wc[QKV3 * IND];   // folded qkv weight: (W_qkv @ w_in) [192,7]
__device__ float g_bc[QKV3];         // folded qkv bias:  W_qkv @ b_in + b_qkv
__device__ float g_qkv[(size_t)ROWS * QKV3];   // [B*T, 192]  (q | k | v)
__device__ float g_ctx[(size_t)ROWS * EE];     // [B*T, 64]
__device__ float g_attn[(size_t)ROWS * EE];    // attn_out [B*T, 64]
__device__ int   g_starts[ROWS];               // boundary flags [B*T]
__device__ float g_means[(size_t)ROWS * EE];   // padded segment means [B*T, 64]

// ---------------------------------------------------------------
// k0: fold input projection into the qkv projection.
// qkv = (x @ w_in^T + b_in) @ W^T + b  ==  x @ (W @ w_in)^T + (W @ b_in + b)
// ---------------------------------------------------------------
__global__ void k0_fold(const float* __restrict__ w_in, const float* __restrict__ b_in,
                        const float* __restrict__ W, const float* __restrict__ bqkv)
{
    int o = threadIdx.x;           // 0..191
    if (o >= QKV3) return;
    float wc[IND];
#pragma unroll
    for (int i = 0; i < IND; i++) wc[i] = 0.f;
    float bc = bqkv[o];
    for (int j = 0; j < EE; j++) {
        float wj = W[o * EE + j];
        bc += wj * b_in[j];
#pragma unroll
        for (int i = 0; i < IND; i++) wc[i] += wj * w_in[j * IND + i];
    }
#pragma unroll
    for (int i = 0; i < IND; i++) g_wc[o * IND + i] = wc[i];
    g_bc[o] = bc;
}

// ---------------------------------------------------------------
// k1: qkv rows directly from x (192x7 folded GEMM). One row per thread.
// ---------------------------------------------------------------
__global__ __launch_bounds__(128) void k1_qkv(const float* __restrict__ x)
{
    __shared__ float Wc[QKV3 * IND];
    __shared__ float bc[QKV3];
    for (int i = threadIdx.x; i < QKV3 * IND; i += 128) Wc[i] = g_wc[i];
    for (int i = threadIdx.x; i < QKV3; i += 128)       bc[i] = g_bc[i];
    __syncthreads();

    int row = blockIdx.x * 128 + threadIdx.x;
    float xr[IND];
#pragma unroll
    for (int i = 0; i < IND; i++) xr[i] = x[(size_t)row * IND + i];

    float4* dst = (float4*)(g_qkv + (size_t)row * QKV3);
    for (int o4 = 0; o4 < QKV3 / 4; o4++) {
        float a[4];
#pragma unroll
        for (int u = 0; u < 4; u++) {
            int o = o4 * 4 + u;
            float s = bc[o];
#pragma unroll
            for (int i = 0; i < IND; i++) s += xr[i] * Wc[o * IND + i];
            a[u] = s;
        }
        float4 r = {a[0], a[1], a[2], a[3]};
        dst[o4] = r;
    }
}

// ---------------------------------------------------------------
// k2: attention. Block = (b, h, q-tile of 256 queries), 128 threads,
// TWO queries per thread. K/V streamed in 64-row chunks, DOUBLE-BUFFERED
// via cp.async (chunk kc+1 copy issues before chunk kc compute -> LDGSTS
// latency hidden under ~5.6k compute cycles/chunk). Score dot-products
// use split accumulators (2 chains/query) so the FMA pipe stays saturated
// even without fast-math reassociation. Scores are tiny (weights ~0.05
// scale) -> exp with no max-subtraction is exact softmax (no overflow).
// __launch_bounds__(128,2): 2 CTAs/SM = 2 warps/SMSP saturates FMA rt=2.
// ---------------------------------------------------------------
__global__ __launch_bounds__(128, 2) void k2_attn()
{
    int bh = blockIdx.x >> 2;          // 4 q-tiles of 256 per (b,h)
    int qt = blockIdx.x & 3;
    int b  = bh >> 1;
    int h  = bh & 1;
    int tq0 = qt * 256 + threadIdx.x;        // query 0
    int tq1 = tq0 + 128;                     // query 1

    __shared__ float Ks[2][64 * DHH];   // 2 x 8KB
    __shared__ float Vs[2][64 * DHH];   // 2 x 8KB  (32KB total)

    const uint32_t ks_s = (uint32_t)__cvta_generic_to_shared(&Ks[0][0]);
    const uint32_t vs_s = (uint32_t)__cvta_generic_to_shared(&Vs[0][0]);

    float qr0[DHH], qr1[DHH];
    {
        const float4* qp0 = (const float4*)(g_qkv + ((size_t)(b * TT + tq0)) * QKV3 + h * DHH);
        const float4* qp1 = (const float4*)(g_qkv + ((size_t)(b * TT + tq1)) * QKV3 + h * DHH);
#pragma unroll
        for (int j = 0; j < 8; j++) {
            float4 v0 = qp0[j];
            qr0[4*j+0] = v0.x * ATTN_SCALE; qr0[4*j+1] = v0.y * ATTN_SCALE;
            qr0[4*j+2] = v0.z * ATTN_SCALE; qr0[4*j+3] = v0.w * ATTN_SCALE;
            float4 v1 = qp1[j];
            qr1[4*j+0] = v1.x * ATTN_SCALE; qr1[4*j+1] = v1.y * ATTN_SCALE;
            qr1[4*j+2] = v1.z * ATTN_SCALE; qr1[4*j+3] = v1.w * ATTN_SCALE;
        }
    }

    float acc0[DHH], acc1[DHH];
#pragma unroll
    for (int j = 0; j < DHH; j++) { acc0[j] = 0.f; acc1[j] = 0.f; }
    float denom0 = 0.f, denom1 = 0.f;

    // issue async copy of chunk kc (64 K-rows + 64 V-rows) into buffer `buf`
    auto issue_copy = [&](int kc, int buf) {
#pragma unroll
        for (int it = 0; it < 4; it++) {
            int l = it * 128 + threadIdx.x;      // 0..511: 64 rows x 8 float4
            int r = l >> 3, j = l & 7;
            const float* base = g_qkv + ((size_t)(b * TT + kc * 64 + r)) * QKV3 + h * DHH;
            uint32_t off = (uint32_t)(buf * 2048 + l * 4) * 4u;   // bytes
            CP_ASYNC16(ks_s + off, base + 64  + j * 4);
            CP_ASYNC16(vs_s + off, base + 128 + j * 4);
        }
        CP_COMMIT();
    };

    issue_copy(0, 0);

    for (int kc = 0; kc < 16; kc++) {
        int cur = kc & 1;
        if (kc < 15) {
            issue_copy(kc + 1, cur ^ 1);   // overlap next copy with this compute
            CP_WAIT(1);                    // chunk kc's group done; kc+1 in flight
        } else {
            CP_WAIT(0);
        }
        __syncthreads();                   // copies visible block-wide

        const float* Kc = Ks[cur];
        const float* Vc = Vs[cur];
        for (int kk = 0; kk < 64; kk++) {
            const float4* kr = (const float4*)(Kc + kk * DHH);
            float s0a = 0.f, s0b = 0.f, s1a = 0.f, s1b = 0.f;
#pragma unroll
            for (int j = 0; j < 8; j += 2) {
                float4 wa = kr[j];
                s0a += qr0[4*j]*wa.x + qr0[4*j+1]*wa.y + qr0[4*j+2]*wa.z + qr0[4*j+3]*wa.w;
                s1a += qr1[4*j]*wa.x + qr1[4*j+1]*wa.y + qr1[4*j+2]*wa.z + qr1[4*j+3]*wa.w;
                float4 wb = kr[j+1];
                s0b += qr0[4*j+4]*wb.x + qr0[4*j+5]*wb.y + qr0[4*j+6]*wb.z + qr0[4*j+7]*wb.w;
                s1b += qr1[4*j+4]*wb.x + qr1[4*j+5]*wb.y + qr1[4*j+6]*wb.z + qr1[4*j+7]*wb.w;
            }
            float p0 = __expf(s0a + s0b);
            float p1 = __expf(s1a + s1b);
            denom0 += p0;
            denom1 += p1;
            const float4* vr = (const float4*)(Vc + kk * DHH);
#pragma unroll
            for (int j = 0; j < 8; j++) {
                float4 w = vr[j];
                acc0[4*j]   += p0 * w.x;  acc0[4*j+1] += p0 * w.y;
                acc0[4*j+2] += p0 * w.z;  acc0[4*j+3] += p0 * w.w;
                acc1[4*j]   += p1 * w.x;  acc1[4*j+1] += p1 * w.y;
                acc1[4*j+2] += p1 * w.z;  acc1[4*j+3] += p1 * w.w;
            }
        }
        __syncthreads();                   // compute done before buffer reuse
    }

    float inv0 = 1.f / denom0;
    float inv1 = 1.f / denom1;
    float4* op0 = (float4*)(g_ctx + ((size_t)(b * TT + tq0)) * EE + h * DHH);
    float4* op1 = (float4*)(g_ctx + ((size_t)(b * TT + tq1)) * EE + h * DHH);
#pragma unroll
    for (int j = 0; j < 8; j++) {
        float4 r0 = {acc0[4*j]*inv0, acc0[4*j+1]*inv0, acc0[4*j+2]*inv0, acc0[4*j+3]*inv0};
        op0[j] = r0;
        float4 r1 = {acc1[4*j]*inv1, acc1[4*j+1]*inv1, acc1[4*j+2]*inv1, acc1[4*j+3]*inv1};
        op1[j] = r1;
    }
}

// ---------------------------------------------------------------
// k3: attn_out = ctx @ out_w^T + out_b, fused with the boundary MLP
// (Linear(64->32) -> ReLU -> Linear(32->1) -> sigmoid > 0.2) -> starts.
// One row per thread; boundary hidden accumulated incrementally.
// ---------------------------------------------------------------
__global__ __launch_bounds__(128) void k3_out_bp(
    const float* __restrict__ out_w, const float* __restrict__ out_b,
    const float* __restrict__ bw1,   const float* __restrict__ bb1,
    const float* __restrict__ bw2,   const float* __restrict__ bb2)
{
    __shared__ float Wo[EE * EE];     // 16KB
    __shared__ float W1t[EE][32];     // bw1 transposed, 8KB
    __shared__ float ob[EE], b1[32], w2[32];
    __shared__ float b2s;
    for (int i = threadIdx.x; i < EE * EE; i += 128) Wo[i] = out_w[i];
    for (int i = threadIdx.x; i < 32 * EE; i += 128) {
        int m = i / EE, o = i % EE;
        W1t[o][m] = bw1[i];
    }
    for (int i = threadIdx.x; i < EE; i += 128) ob[i] = out_b[i];
    if (threadIdx.x < 32) { b1[threadIdx.x] = bb1[threadIdx.x]; w2[threadIdx.x] = bw2[threadIdx.x]; }
    if (threadIdx.x == 0) b2s = bb2[0];
    __syncthreads();

    int row = blockIdx.x * 128 + threadIdx.x;

    float c[EE];
    const float4* cp = (const float4*)(g_ctx + (size_t)row * EE);
#pragma unroll
    for (int j = 0; j < 16; j++) {
        float4 v = cp[j];
        c[4*j] = v.x; c[4*j+1] = v.y; c[4*j+2] = v.z; c[4*j+3] = v.w;
    }

    float hid[32];
#pragma unroll
    for (int m = 0; m < 32; m++) hid[m] = b1[m];

    float4* ap = (float4*)(g_attn + (size_t)row * EE);
    for (int o4 = 0; o4 < 16; o4++) {
        float a[4];
#pragma unroll
        for (int u = 0; u < 4; u++) {
            int o = o4 * 4 + u;
            float s = ob[o];
            const float4* wr = (const float4*)(Wo + o * EE);
#pragma unroll
            for (int j = 0; j < 16; j++) {
                float4 w = wr[j];
                s += c[4*j]*w.x + c[4*j+1]*w.y + c[4*j+2]*w.z + c[4*j+3]*w.w;
            }
            a[u] = s;
#pragma unroll
            for (int m = 0; m < 32; m++) hid[m] += s * W1t[o][m];
        }
        float4 r = {a[0], a[1], a[2], a[3]};
        ap[o4] = r;
    }

    float z = b2s;
#pragma unroll
    for (int m = 0; m < 32; m++) z += fmaxf(hid[m], 0.f) * w2[m];
    float bs = 1.f / (1.f + __expf(-z));

    int t = row & (TT - 1);
    g_starts[row] = (t == 0) || ((t <= TT - 2) && (bs > 0.2f));
}

// ---------------------------------------------------------------
// k4: segment means. Block = batch, thread = channel e.
// Sequential sweep over T (segments are contiguous in time), fully
// deterministic (no atomics). Loads hoisted + unroll 8 for MLP (only
// 64 CTAs resident -> per-CTA latency matters). Tail rows zeroed
// (reference: cnt=0 -> mean 0).
// ---------------------------------------------------------------
__global__ __launch_bounds__(64) void k4_means()
{
    int b = blockIdx.x;
    int e = threadIdx.x;
    __shared__ int ss[TT];
    for (int i = threadIdx.x; i < TT; i += 64) ss[i] = g_starts[b * TT + i];
    __syncthreads();

    const float* ap = g_attn  + (size_t)b * TT * EE + e;
    float*       mp = g_means + (size_t)b * TT * EE + e;

    float sum = 0.f, cnt = 0.f;
    int seg = -1;
#pragma unroll 8
    for (int t = 0; t < TT; t++) {
        float av = ap[(size_t)t * EE];      // load issued before branch (MLP)
        if (ss[t]) {                        // block-uniform branch
            if (seg >= 0) mp[(size_t)seg * EE] = sum / cnt;
            seg++; sum = 0.f; cnt = 0.f;
        }
        sum += av;
        cnt += 1.f;
    }
    mp[(size_t)seg * EE] = sum / cnt;
    for (int s = seg + 1; s < TT; s++) mp[(size_t)s * EE] = 0.f;
}

// ---------------------------------------------------------------
// k5: out = padded_means @ proj_w^T + proj_b. One row per thread.
// ---------------------------------------------------------------
__global__ __launch_bounds__(128) void k5_proj(const float* __restrict__ pw,
                                               const float* __restrict__ pb,
                                               float* __restrict__ out)
{
    __shared__ float Pw[EE * EE];
    __shared__ float Pb[EE];
    for (int i = threadIdx.x; i < EE * EE; i += 128) Pw[i] = pw[i];
    for (int i = threadIdx.x; i < EE; i += 128) Pb[i] = pb[i];
    __syncthreads();

    int row = blockIdx.x * 128 + threadIdx.x;
    float m[EE];
    const float4* mp = (const float4*)(g_means + (size_t)row * EE);
#pragma unroll
    for (int j = 0; j < 16; j++) {
        float4 v = mp[j];
        m[4*j] = v.x; m[4*j+1] = v.y; m[4*j+2] = v.z; m[4*j+3] = v.w;
    }

    float4* op = (float4*)(out + (size_t)row * EE);
    for (int o4 = 0; o4 < 16; o4++) {
        float a[4];
#pragma unroll
        for (int u = 0; u < 4; u++) {
            int o = o4 * 4 + u;
            float s = Pb[o];
            const float4* wr = (const float4*)(Pw + o * EE);
#pragma unroll
            for (int j = 0; j < 16; j++) {
                float4 w = wr[j];
                s += m[4*j]*w.x + m[4*j+1]*w.y + m[4*j+2]*w.z + m[4*j+3]*w.w;
            }
            a[u] = s;
        }
        float4 r = {a[0], a[1], a[2], a[3]};
        op[o4] = r;
    }
}

// ---------------------------------------------------------------
extern "C" void kernel_launch(void* const* d_in, const int* in_sizes, int n_in,
                              void* d_out, int out_size)
{
    const float* x    = (const float*)d_in[0];
    const float* w_in = (const float*)d_in[1];
    const float* b_in = (const float*)d_in[2];
    const float* ipw  = (const float*)d_in[3];
    const float* ipb  = (const float*)d_in[4];
    const float* ow   = (const float*)d_in[5];
    const float* obv  = (const float*)d_in[6];
    const float* b1w  = (const float*)d_in[7];
    const float* b1b  = (const float*)d_in[8];
    const float* b2w  = (const float*)d_in[9];
    const float* b2b  = (const float*)d_in[10];
    const float* pw   = (const float*)d_in[11];
    const float* pb   = (const float*)d_in[12];
    float* out = (float*)d_out;

    k0_fold<<<1, QKV3>>>(w_in, b_in, ipw, ipb);
    k1_qkv<<<ROWS / 128, 128>>>(x);
    k2_attn<<<BB * HH * (TT / 256), 128>>>();
    k3_out_bp<<<ROWS / 128, 128>>>(ow, obv, b1w, b1b, b2w, b2b);
    k4_means<<<BB, 64>>>();
    k5_proj<<<ROWS / 128, 128>>>(pw, pb, out);
}

// round 6
// speedup vs baseline: 1.1470x; 1.1470x over previous
#include <cuda_runtime.h>
#include <cstdint>

#define BB   64
#define TT   1024
#define IND  7
#define EE   64
#define HH   2
#define DHH  32
#define QKV3 192
#define ROWS (BB*TT)

#define ATTN_SCALE 0.17677669529663687f  // 1/sqrt(32)

typedef unsigned long long u64;

// Blackwell packed 2xfp32 FMA (FFMA2): d = a*b + c on both lanes
#define FMA2(d, a, b, c) \
    asm("fma.rn.f32x2 %0, %1, %2, %3;" : "=l"(d) : "l"(a), "l"(b), "l"(c))
#define ADD2(d, a, b) \
    asm("add.rn.f32x2 %0, %1, %2;" : "=l"(d) : "l"(a), "l"(b))
#define PACK2(d, lo, hi) \
    asm("mov.b64 %0, {%1, %2};" : "=l"(d) : "f"(lo), "f"(hi))
#define UNPACK2(lo, hi, s) \
    asm("mov.b64 {%0, %1}, %2;" : "=f"(lo), "=f"(hi) : "l"(s))
// one LDS.128 delivering two packed u64 (f32x2) operands
#define LDS128_U64(a, b, addr) \
    asm("ld.shared.v2.u64 {%0, %1}, [%2];" : "=l"(a), "=l"(b) : "r"(addr))

// cp.async 16B: global -> shared, L2-only cache policy (.cg)
#define CP_ASYNC16(dst_u32, src_ptr) \
    asm volatile("cp.async.cg.shared.global [%0], [%1], 16;" :: "r"(dst_u32), "l"(src_ptr) : "memory")
#define CP_COMMIT()   asm volatile("cp.async.commit_group;" ::: "memory")
#define CP_WAIT(N)    asm volatile("cp.async.wait_group %0;" :: "n"(N) : "memory")

// ---------- scratch (device globals; no allocation allowed) ----------
__device__ float g_wc[QKV3 * IND];   // folded qkv weight: (W_qkv @ w_in) [192,7]
__device__ float g_bc[QKV3];         // folded qkv bias:  W_qkv @ b_in + b_qkv
__device__ float g_qkv[(size_t)ROWS * QKV3];   // [B*T, 192]  (q | k | v)
__device__ float g_ctx[(size_t)ROWS * EE];     // [B*T, 64]
__device__ float g_attn[(size_t)ROWS * EE];    // attn_out [B*T, 64]
__device__ int   g_starts[ROWS];               // boundary flags [B*T]
__device__ float g_means[(size_t)ROWS * EE];   // padded segment means [B*T, 64]

// ---------------------------------------------------------------
// k0: fold input projection into the qkv projection.
// qkv = (x @ w_in^T + b_in) @ W^T + b  ==  x @ (W @ w_in)^T + (W @ b_in + b)
// ---------------------------------------------------------------
__global__ void k0_fold(const float* __restrict__ w_in, const float* __restrict__ b_in,
                        const float* __restrict__ W, const float* __restrict__ bqkv)
{
    int o = threadIdx.x;           // 0..191
    if (o >= QKV3) return;
    float wc[IND];
#pragma unroll
    for (int i = 0; i < IND; i++) wc[i] = 0.f;
    float bc = bqkv[o];
    for (int j = 0; j < EE; j++) {
        float wj = W[o * EE + j];
        bc += wj * b_in[j];
#pragma unroll
        for (int i = 0; i < IND; i++) wc[i] += wj * w_in[j * IND + i];
    }
#pragma unroll
    for (int i = 0; i < IND; i++) g_wc[o * IND + i] = wc[i];
    g_bc[o] = bc;
}

// ---------------------------------------------------------------
// k1: qkv rows directly from x (192x7 folded GEMM). One row per thread.
// ---------------------------------------------------------------
__global__ __launch_bounds__(128) void k1_qkv(const float* __restrict__ x)
{
    __shared__ float Wc[QKV3 * IND];
    __shared__ float bc[QKV3];
    for (int i = threadIdx.x; i < QKV3 * IND; i += 128) Wc[i] = g_wc[i];
    for (int i = threadIdx.x; i < QKV3; i += 128)       bc[i] = g_bc[i];
    __syncthreads();

    int row = blockIdx.x * 128 + threadIdx.x;
    float xr[IND];
#pragma unroll
    for (int i = 0; i < IND; i++) xr[i] = x[(size_t)row * IND + i];

    float4* dst = (float4*)(g_qkv + (size_t)row * QKV3);
    for (int o4 = 0; o4 < QKV3 / 4; o4++) {
        float a[4];
#pragma unroll
        for (int u = 0; u < 4; u++) {
            int o = o4 * 4 + u;
            float s = bc[o];
#pragma unroll
            for (int i = 0; i < IND; i++) s += xr[i] * Wc[o * IND + i];
            a[u] = s;
        }
        float4 r = {a[0], a[1], a[2], a[3]};
        dst[o4] = r;
    }
}

// ---------------------------------------------------------------
// k2: attention. Block = (b, h, q-tile of 256 queries), 128 threads,
// TWO queries per thread. K/V streamed in 64-row chunks, double-buffered
// via cp.async. Inner loops use Blackwell packed fp32x2 FMA (FFMA2):
// 2 MACs per fma-pipe issue slot -> halves the pipe-bound core time vs
// scalar FFMA. K/V read from smem as u64 pairs via ld.shared.v2.u64
// (still LDS.128, zero packing MOVs). Scores are tiny (~0.015) -> exp
// with no max-subtraction is exact softmax (no overflow possible).
// ---------------------------------------------------------------
__global__ __launch_bounds__(128, 2) void k2_attn()
{
    int bh = blockIdx.x >> 2;          // 4 q-tiles of 256 per (b,h)
    int qt = blockIdx.x & 3;
    int b  = bh >> 1;
    int h  = bh & 1;
    int tq0 = qt * 256 + threadIdx.x;        // query 0
    int tq1 = tq0 + 128;                     // query 1

    __shared__ float Ks[2][64 * DHH];   // 2 x 8KB
    __shared__ float Vs[2][64 * DHH];   // 2 x 8KB  (32KB total)

    const uint32_t ks_s = (uint32_t)__cvta_generic_to_shared(&Ks[0][0]);
    const uint32_t vs_s = (uint32_t)__cvta_generic_to_shared(&Vs[0][0]);

    // q packed as f32x2: 16 u64 per query
    u64 qr0[16], qr1[16];
    {
        const float4* qp0 = (const float4*)(g_qkv + ((size_t)(b * TT + tq0)) * QKV3 + h * DHH);
        const float4* qp1 = (const float4*)(g_qkv + ((size_t)(b * TT + tq1)) * QKV3 + h * DHH);
#pragma unroll
        for (int j = 0; j < 8; j++) {
            float4 v0 = qp0[j];
            PACK2(qr0[2*j],   v0.x * ATTN_SCALE, v0.y * ATTN_SCALE);
            PACK2(qr0[2*j+1], v0.z * ATTN_SCALE, v0.w * ATTN_SCALE);
            float4 v1 = qp1[j];
            PACK2(qr1[2*j],   v1.x * ATTN_SCALE, v1.y * ATTN_SCALE);
            PACK2(qr1[2*j+1], v1.z * ATTN_SCALE, v1.w * ATTN_SCALE);
        }
    }

    // packed accumulators: 16 u64 per query
    u64 acc0[16], acc1[16];
#pragma unroll
    for (int j = 0; j < 16; j++) { acc0[j] = 0ull; acc1[j] = 0ull; }
    float denom0 = 0.f, denom1 = 0.f;

    // issue async copy of chunk kc (64 K-rows + 64 V-rows) into buffer `buf`
    auto issue_copy = [&](int kc, int buf) {
#pragma unroll
        for (int it = 0; it < 4; it++) {
            int l = it * 128 + threadIdx.x;      // 0..511: 64 rows x 8 float4
            int r = l >> 3, j = l & 7;
            const float* base = g_qkv + ((size_t)(b * TT + kc * 64 + r)) * QKV3 + h * DHH;
            uint32_t off = (uint32_t)(buf * 2048 + l * 4) * 4u;   // bytes
            CP_ASYNC16(ks_s + off, base + 64  + j * 4);
            CP_ASYNC16(vs_s + off, base + 128 + j * 4);
        }
        CP_COMMIT();
    };

    issue_copy(0, 0);

    for (int kc = 0; kc < 16; kc++) {
        int cur = kc & 1;
        if (kc < 15) {
            issue_copy(kc + 1, cur ^ 1);   // overlap next copy with this compute
            CP_WAIT(1);                    // chunk kc's group done; kc+1 in flight
        } else {
            CP_WAIT(0);
        }
        __syncthreads();                   // copies visible block-wide

        const uint32_t kbase = ks_s + (uint32_t)cur * 8192u;
        const uint32_t vbase = vs_s + (uint32_t)cur * 8192u;
        for (int kk = 0; kk < 64; kk++) {
            uint32_t ka = kbase + (uint32_t)kk * 128u;
            u64 s0A = 0ull, s0B = 0ull, s1A = 0ull, s1B = 0ull;
#pragma unroll
            for (int j = 0; j < 8; j++) {
                u64 a, c;
                LDS128_U64(a, c, ka + j * 16u);
                FMA2(s0A, qr0[2*j],   a, s0A);
                FMA2(s0B, qr0[2*j+1], c, s0B);
                FMA2(s1A, qr1[2*j],   a, s1A);
                FMA2(s1B, qr1[2*j+1], c, s1B);
            }
            u64 s0p, s1p;
            ADD2(s0p, s0A, s0B);
            ADD2(s1p, s1A, s1B);
            float s0lo, s0hi, s1lo, s1hi;
            UNPACK2(s0lo, s0hi, s0p);
            UNPACK2(s1lo, s1hi, s1p);
            float p0 = __expf(s0lo + s0hi);
            float p1 = __expf(s1lo + s1hi);
            denom0 += p0;
            denom1 += p1;
            u64 pp0, pp1;
            PACK2(pp0, p0, p0);
            PACK2(pp1, p1, p1);
            uint32_t va = vbase + (uint32_t)kk * 128u;
#pragma unroll
            for (int j = 0; j < 8; j++) {
                u64 a, c;
                LDS128_U64(a, c, va + j * 16u);
                FMA2(acc0[2*j],   pp0, a, acc0[2*j]);
                FMA2(acc0[2*j+1], pp0, c, acc0[2*j+1]);
                FMA2(acc1[2*j],   pp1, a, acc1[2*j]);
                FMA2(acc1[2*j+1], pp1, c, acc1[2*j+1]);
            }
        }
        __syncthreads();                   // compute done before buffer reuse
    }

    float inv0 = 1.f / denom0;
    float inv1 = 1.f / denom1;
    float4* op0 = (float4*)(g_ctx + ((size_t)(b * TT + tq0)) * EE + h * DHH);
    float4* op1 = (float4*)(g_ctx + ((size_t)(b * TT + tq1)) * EE + h * DHH);
#pragma unroll
    for (int j = 0; j < 8; j++) {
        float a0, b0, c0, d0, a1, b1, c1, d1;
        UNPACK2(a0, b0, acc0[2*j]);
        UNPACK2(c0, d0, acc0[2*j+1]);
        UNPACK2(a1, b1, acc1[2*j]);
        UNPACK2(c1, d1, acc1[2*j+1]);
        float4 r0 = {a0*inv0, b0*inv0, c0*inv0, d0*inv0};
        op0[j] = r0;
        float4 r1 = {a1*inv1, b1*inv1, c1*inv1, d1*inv1};
        op1[j] = r1;
    }
}

// ---------------------------------------------------------------
// k3: attn_out = ctx @ out_w^T + out_b, fused with the boundary MLP
// (Linear(64->32) -> ReLU -> Linear(32->1) -> sigmoid > 0.2) -> starts.
// TWO rows per thread, processed sequentially (same register footprint,
// amortizes the 25KB smem weight preamble that ncu showed dominating:
// occ 16.8%, issue 35.9% -> latency-bound on the block prologue).
// ---------------------------------------------------------------
__global__ __launch_bounds__(128) void k3_out_bp(
    const float* __restrict__ out_w, const float* __restrict__ out_b,
    const float* __restrict__ bw1,   const float* __restrict__ bb1,
    const float* __restrict__ bw2,   const float* __restrict__ bb2)
{
    __shared__ float Wo[EE * EE];     // 16KB
    __shared__ float W1t[EE][32];     // bw1 transposed, 8KB
    __shared__ float ob[EE], b1[32], w2[32];
    __shared__ float b2s;
    for (int i = threadIdx.x; i < EE * EE; i += 128) Wo[i] = out_w[i];
    for (int i = threadIdx.x; i < 32 * EE; i += 128) {
        int m = i / EE, o = i % EE;
        W1t[o][m] = bw1[i];
    }
    for (int i = threadIdx.x; i < EE; i += 128) ob[i] = out_b[i];
    if (threadIdx.x < 32) { b1[threadIdx.x] = bb1[threadIdx.x]; w2[threadIdx.x] = bw2[threadIdx.x]; }
    if (threadIdx.x == 0) b2s = bb2[0];
    __syncthreads();

#pragma unroll 1
    for (int rr = 0; rr < 2; rr++) {
        int row = blockIdx.x * 256 + rr * 128 + threadIdx.x;

        float c[EE];
        const float4* cp = (const float4*)(g_ctx + (size_t)row * EE);
#pragma unroll
        for (int j = 0; j < 16; j++) {
            float4 v = cp[j];
            c[4*j] = v.x; c[4*j+1] = v.y; c[4*j+2] = v.z; c[4*j+3] = v.w;
        }

        float hid[32];
#pragma unroll
        for (int m = 0; m < 32; m++) hid[m] = b1[m];

        float4* ap = (float4*)(g_attn + (size_t)row * EE);
        for (int o4 = 0; o4 < 16; o4++) {
            float a[4];
#pragma unroll
            for (int u = 0; u < 4; u++) {
                int o = o4 * 4 + u;
                float s = ob[o];
                const float4* wr = (const float4*)(Wo + o * EE);
#pragma unroll
                for (int j = 0; j < 16; j++) {
                    float4 w = wr[j];
                    s += c[4*j]*w.x + c[4*j+1]*w.y + c[4*j+2]*w.z + c[4*j+3]*w.w;
                }
                a[u] = s;
#pragma unroll
                for (int m = 0; m < 32; m++) hid[m] += s * W1t[o][m];
            }
            float4 r = {a[0], a[1], a[2], a[3]};
            ap[o4] = r;
        }

        float z = b2s;
#pragma unroll
        for (int m = 0; m < 32; m++) z += fmaxf(hid[m], 0.f) * w2[m];
        float bs = 1.f / (1.f + __expf(-z));

        int t = row & (TT - 1);
        g_starts[row] = (t == 0) || ((t <= TT - 2) && (bs > 0.2f));
    }
}

// ---------------------------------------------------------------
// k4: segment means. Block = batch, thread = channel e.
// Sequential sweep over T (segments are contiguous in time), fully
// deterministic (no atomics). Loads hoisted + unroll 8 for MLP (only
// 64 CTAs resident -> per-CTA latency matters). Tail rows zeroed
// (reference: cnt=0 -> mean 0).
// ---------------------------------------------------------------
__global__ __launch_bounds__(64) void k4_means()
{
    int b = blockIdx.x;
    int e = threadIdx.x;
    __shared__ int ss[TT];
    for (int i = threadIdx.x; i < TT; i += 64) ss[i] = g_starts[b * TT + i];
    __syncthreads();

    const float* ap = g_attn  + (size_t)b * TT * EE + e;
    float*       mp = g_means + (size_t)b * TT * EE + e;

    float sum = 0.f, cnt = 0.f;
    int seg = -1;
#pragma unroll 8
    for (int t = 0; t < TT; t++) {
        float av = ap[(size_t)t * EE];      // load issued before branch (MLP)
        if (ss[t]) {                        // block-uniform branch
            if (seg >= 0) mp[(size_t)seg * EE] = sum / cnt;
            seg++; sum = 0.f; cnt = 0.f;
        }
        sum += av;
        cnt += 1.f;
    }
    mp[(size_t)seg * EE] = sum / cnt;
    for (int s = seg + 1; s < TT; s++) mp[(size_t)s * EE] = 0.f;
}

// ---------------------------------------------------------------
// k5: out = padded_means @ proj_w^T + proj_b. TWO rows per thread
// (sequential), amortizing the 16KB weight preamble like k3.
// ---------------------------------------------------------------
__global__ __launch_bounds__(128) void k5_proj(const float* __restrict__ pw,
                                               const float* __restrict__ pb,
                                               float* __restrict__ out)
{
    __shared__ float Pw[EE * EE];
    __shared__ float Pb[EE];
    for (int i = threadIdx.x; i < EE * EE; i += 128) Pw[i] = pw[i];
    for (int i = threadIdx.x; i < EE; i += 128) Pb[i] = pb[i];
    __syncthreads();

#pragma unroll 1
    for (int rr = 0; rr < 2; rr++) {
        int row = blockIdx.x * 256 + rr * 128 + threadIdx.x;
        float m[EE];
        const float4* mp = (const float4*)(g_means + (size_t)row * EE);
#pragma unroll
        for (int j = 0; j < 16; j++) {
            float4 v = mp[j];
            m[4*j] = v.x; m[4*j+1] = v.y; m[4*j+2] = v.z; m[4*j+3] = v.w;
        }

        float4* op = (float4*)(out + (size_t)row * EE);
        for (int o4 = 0; o4 < 16; o4++) {
            float a[4];
#pragma unroll
            for (int u = 0; u < 4; u++) {
                int o = o4 * 4 + u;
                float s = Pb[o];
                const float4* wr = (const float4*)(Pw + o * EE);
#pragma unroll
                for (int j = 0; j < 16; j++) {
                    float4 w = wr[j];
                    s += m[4*j]*w.x + m[4*j+1]*w.y + m[4*j+2]*w.z + m[4*j+3]*w.w;
                }
                a[u] = s;
            }
            float4 r = {a[0], a[1], a[2], a[3]};
            op[o4] = r;
        }
    }
}

// ---------------------------------------------------------------
extern "C" void kernel_launch(void* const* d_in, const int* in_sizes, int n_in,
                              void* d_out, int out_size)
{
    const float* x    = (const float*)d_in[0];
    const float* w_in = (const float*)d_in[1];
    const float* b_in = (const float*)d_in[2];
    const float* ipw  = (const float*)d_in[3];
    const float* ipb  = (const float*)d_in[4];
    const float* ow   = (const float*)d_in[5];
    const float* obv  = (const float*)d_in[6];
    const float* b1w  = (const float*)d_in[7];
    const float* b1b  = (const float*)d_in[8];
    const float* b2w  = (const float*)d_in[9];
    const float* b2b  = (const float*)d_in[10];
    const float* pw   = (const float*)d_in[11];
    const float* pb   = (const float*)d_in[12];
    float* out = (float*)d_out;

    k0_fold<<<1, QKV3>>>(w_in, b_in, ipw, ipb);
    k1_qkv<<<ROWS / 128, 128>>>(x);
    k2_attn<<<BB * HH * (TT / 256), 128>>>();
    k3_out_bp<<<ROWS / 256, 128>>>(ow, obv, b1w, b1b, b2w, b2b);
    k4_means<<<BB, 64>>>();
    k5_proj<<<ROWS / 256, 128>>>(pw, pb, out);
}

// round 7
// speedup vs baseline: 1.8291x; 1.5947x over previous
#include <cuda_runtime.h>
#include <cstdint>

#define BB   64
#define TT   1024
#define IND  7
#define EE   64
#define HH   2
#define DHH  32
#define QKV3 192
#define ROWS (BB*TT)

#define ATTN_SCALE 0.17677669529663687f  // 1/sqrt(32)

// cp.async 16B: global -> shared
#define CP_ASYNC16(dst_u32, src_ptr) \
    asm volatile("cp.async.cg.shared.global [%0], [%1], 16;" :: "r"(dst_u32), "l"(src_ptr) : "memory")
#define CP_COMMIT()   asm volatile("cp.async.commit_group;" ::: "memory")
#define CP_WAIT(N)    asm volatile("cp.async.wait_group %0;" :: "n"(N) : "memory")

// tf32 round-to-nearest (result is an f32 bit pattern with tf32 precision)
#define CVT_TF32(u, f) asm("cvt.rna.tf32.f32 %0, %1;" : "=r"(u) : "f"(f))

// m16n8k8 tf32 MMA, D += A*B (C==D registers)
#define MMA16N8K8(d, a, b) \
    asm volatile("mma.sync.aligned.m16n8k8.row.col.f32.tf32.tf32.f32 " \
        "{%0,%1,%2,%3}, {%4,%5,%6,%7}, {%8,%9}, {%0,%1,%2,%3};" \
        : "+f"((d)[0]), "+f"((d)[1]), "+f"((d)[2]), "+f"((d)[3]) \
        : "r"((a)[0]), "r"((a)[1]), "r"((a)[2]), "r"((a)[3]), "r"((b)[0]), "r"((b)[1]))

// ---------- scratch (device globals; no allocation allowed) ----------
__device__ float g_wc[QKV3 * IND];             // folded qkv weight [192,7]
__device__ float g_bc[QKV3];                   // folded qkv bias
__device__ float g_qkv[(size_t)ROWS * 128];    // [B*T, 128] (q | k), tf32-rounded
__device__ float g_vt[(size_t)BB * HH * DHH * TT]; // V^T [b,h][dh][T], tf32-rounded
__device__ float g_ctx[(size_t)ROWS * EE];     // [B*T, 64]
__device__ float g_attn[(size_t)ROWS * EE];    // attn_out [B*T, 64]
__device__ int   g_starts[ROWS];               // boundary flags [B*T]
__device__ float g_means[(size_t)ROWS * EE];   // padded segment means [B*T, 64]

// ---------------------------------------------------------------
// k0: fold input projection into the qkv projection.
// ---------------------------------------------------------------
__global__ void k0_fold(const float* __restrict__ w_in, const float* __restrict__ b_in,
                        const float* __restrict__ W, const float* __restrict__ bqkv)
{
    int o = threadIdx.x;           // 0..191
    if (o >= QKV3) return;
    float wc[IND];
#pragma unroll
    for (int i = 0; i < IND; i++) wc[i] = 0.f;
    float bc = bqkv[o];
    for (int j = 0; j < EE; j++) {
        float wj = W[o * EE + j];
        bc += wj * b_in[j];
#pragma unroll
        for (int i = 0; i < IND; i++) wc[i] += wj * w_in[j * IND + i];
    }
#pragma unroll
    for (int i = 0; i < IND; i++) g_wc[o * IND + i] = wc[i];
    g_bc[o] = bc;
}

// ---------------------------------------------------------------
// k1: qkv rows from x (192x7 folded GEMM). One row per thread.
// Q,K written tf32-rounded to g_qkv [row][128]; V written tf32-rounded
// and TRANSPOSED to g_vt[b,h][dh][T] (coalesced: consecutive threads =
// consecutive t).
// ---------------------------------------------------------------
__global__ __launch_bounds__(128) void k1_qkv(const float* __restrict__ x)
{
    __shared__ float Wc[QKV3 * IND];
    __shared__ float bc[QKV3];
    for (int i = threadIdx.x; i < QKV3 * IND; i += 128) Wc[i] = g_wc[i];
    for (int i = threadIdx.x; i < QKV3; i += 128)       bc[i] = g_bc[i];
    __syncthreads();

    int row = blockIdx.x * 128 + threadIdx.x;
    int b_  = row >> 10;
    int t_  = row & (TT - 1);

    float xr[IND];
#pragma unroll
    for (int i = 0; i < IND; i++) xr[i] = x[(size_t)row * IND + i];

    float4* dst = (float4*)(g_qkv + (size_t)row * 128);
    for (int o4 = 0; o4 < 48; o4++) {
        float a[4];
#pragma unroll
        for (int u = 0; u < 4; u++) {
            int o = o4 * 4 + u;
            float s = bc[o];
#pragma unroll
            for (int i = 0; i < IND; i++) s += xr[i] * Wc[o * IND + i];
            uint32_t ub; CVT_TF32(ub, s);
            a[u] = __uint_as_float(ub);
        }
        if (o4 < 32) {
            float4 r = {a[0], a[1], a[2], a[3]};
            dst[o4] = r;
        } else {
#pragma unroll
            for (int u = 0; u < 4; u++) {
                int o = o4 * 4 + u;           // 128..191
                int h = (o - 128) >> 5;
                int d = (o - 128) & 31;
                g_vt[((size_t)((b_ * HH + h) * DHH + d)) * TT + t_] = a[u];
            }
        }
    }
}

// ---------------------------------------------------------------
// k2: tf32 tensor-core flash attention (mma.sync m16n8k8).
// Block = (b, h, q-tile of 128). 4 warps, warp = 32 queries (2 m16 tiles).
// Keys streamed in 128-key chunks: K [128][36-padded] + Vt [32][140-padded]
// in smem via cp.async. Per 8-key group: S = Q K^T (8 HMMA), exp (fp32),
// P reused in-register as the A operand of P@V (8 HMMA) via the key
// permutation pi(n) = (n>>1) + (n&1)*4 applied to K fragment addressing.
// Scores tiny -> exp without max-subtraction is exact softmax.
// Scale folded into the exp argument so Q/K stay exactly tf32.
// ---------------------------------------------------------------
__global__ __launch_bounds__(128) void k2_attn()
{
    int qt = blockIdx.x & 7;
    int h  = (blockIdx.x >> 3) & 1;
    int b  = blockIdx.x >> 4;

    __shared__ float Ks[128 * 36];   // 18432 B, padded rows (conflict-free frags)
    __shared__ float Vt[32 * 140];   // 17920 B, padded rows

    const uint32_t ks_s = (uint32_t)__cvta_generic_to_shared(Ks);
    const uint32_t vt_s = (uint32_t)__cvta_generic_to_shared(Vt);

    int tid  = threadIdx.x;
    int w    = tid >> 5;
    int lane = tid & 31;
    int g    = lane >> 2;     // 0..7
    int t    = lane & 3;      // 0..3
    int qb   = qt * 128 + w * 32;

    // ---- load Q A-fragments (already tf32 bit patterns) ----
    uint32_t A[2][4][4];
#pragma unroll
    for (int m = 0; m < 2; m++) {
        const float* q0 = g_qkv + ((size_t)(b * TT + qb + m * 16 + g)) * 128 + h * 32;
        const float* q1 = q0 + 8 * 128;
#pragma unroll
        for (int s = 0; s < 4; s++) {
            A[m][s][0] = __float_as_uint(q0[s * 8 + t]);
            A[m][s][1] = __float_as_uint(q1[s * 8 + t]);
            A[m][s][2] = __float_as_uint(q0[s * 8 + t + 4]);
            A[m][s][3] = __float_as_uint(q1[s * 8 + t + 4]);
        }
    }

    float ctx[2][4][4];
#pragma unroll
    for (int m = 0; m < 2; m++)
#pragma unroll
        for (int j = 0; j < 4; j++)
#pragma unroll
            for (int u = 0; u < 4; u++) ctx[m][j][u] = 0.f;
    float ds[2][2] = {{0.f, 0.f}, {0.f, 0.f}};

    int pk_off = (g >> 1) + ((g & 1) << 2);   // key permutation pi(g)

#pragma unroll 1
    for (int kc = 0; kc < 8; kc++) {
        // ---- async load K chunk [128][32] and Vt chunk [32][128] ----
        {
            const float* ksrc = g_qkv + ((size_t)(b * TT + kc * 128 + tid)) * 128 + 64 + h * 32;
            uint32_t kdst = ks_s + (uint32_t)tid * 144u;
#pragma unroll
            for (int s = 0; s < 8; s++) CP_ASYNC16(kdst + s * 16u, ksrc + s * 4);
            int dh = tid >> 2, q4 = tid & 3;
            const float* vsrc = g_vt + ((size_t)((b * HH + h) * DHH + dh)) * TT + kc * 128 + q4 * 32;
            uint32_t vdst = vt_s + (uint32_t)dh * 560u + (uint32_t)q4 * 128u;
#pragma unroll
            for (int s = 0; s < 8; s++) CP_ASYNC16(vdst + s * 16u, vsrc + s * 4);
            CP_COMMIT();
            CP_WAIT(0);
        }
        __syncthreads();

#pragma unroll 2
        for (int grp = 0; grp < 16; grp++) {
            // K B-fragments (permuted key row)
            int pk = grp * 8 + pk_off;
            uint32_t kb[4][2];
#pragma unroll
            for (int s = 0; s < 4; s++) {
                kb[s][0] = __float_as_uint(Ks[pk * 36 + s * 8 + t]);
                kb[s][1] = __float_as_uint(Ks[pk * 36 + s * 8 + t + 4]);
            }
            // Vt B-fragments (natural key order)
            uint32_t vb[4][2];
#pragma unroll
            for (int j = 0; j < 4; j++) {
                vb[j][0] = __float_as_uint(Vt[(j * 8 + g) * 140 + grp * 8 + t]);
                vb[j][1] = __float_as_uint(Vt[(j * 8 + g) * 140 + grp * 8 + t + 4]);
            }
#pragma unroll
            for (int m = 0; m < 2; m++) {
                float c[4] = {0.f, 0.f, 0.f, 0.f};
#pragma unroll
                for (int s = 0; s < 4; s++) MMA16N8K8(c, A[m][s], kb[s]);
                // exp(scale * s); permutation maps C frag -> P A-frag directly:
                // a0=(row g,key t)<-c0, a1=(g+8,t)<-c2, a2=(g,t+4)<-c1, a3=(g+8,t+4)<-c3
                float p0 = __expf(c[0] * ATTN_SCALE);
                float p1 = __expf(c[2] * ATTN_SCALE);
                float p2 = __expf(c[1] * ATTN_SCALE);
                float p3 = __expf(c[3] * ATTN_SCALE);
                ds[m][0] += p0 + p2;     // row g
                ds[m][1] += p1 + p3;     // row g+8
                uint32_t pa[4];
                CVT_TF32(pa[0], p0);
                CVT_TF32(pa[1], p1);
                CVT_TF32(pa[2], p2);
                CVT_TF32(pa[3], p3);
#pragma unroll
                for (int j = 0; j < 4; j++) MMA16N8K8(ctx[m][j], pa, vb[j]);
            }
        }
        __syncthreads();
    }

    // ---- reduce denominators across the quad (lanes sharing a row) ----
#pragma unroll
    for (int m = 0; m < 2; m++)
#pragma unroll
        for (int i = 0; i < 2; i++) {
            ds[m][i] += __shfl_xor_sync(0xffffffffu, ds[m][i], 1);
            ds[m][i] += __shfl_xor_sync(0xffffffffu, ds[m][i], 2);
        }

    // ---- normalize + write ctx ----
#pragma unroll
    for (int m = 0; m < 2; m++) {
        float inv0 = 1.f / ds[m][0];
        float inv1 = 1.f / ds[m][1];
        int r0 = b * TT + qb + m * 16 + g;
        float* o0 = g_ctx + (size_t)r0 * EE + h * DHH;
        float* o1 = o0 + 8 * EE;
#pragma unroll
        for (int j = 0; j < 4; j++) {
            float2 lo = {ctx[m][j][0] * inv0, ctx[m][j][1] * inv0};
            float2 hi = {ctx[m][j][2] * inv1, ctx[m][j][3] * inv1};
            *(float2*)(o0 + j * 8 + 2 * t) = lo;
            *(float2*)(o1 + j * 8 + 2 * t) = hi;
        }
    }
}

// ---------------------------------------------------------------
// k3: attn_out = ctx @ out_w^T + out_b, fused with the boundary MLP.
// TWO rows per thread (amortizes the 25KB smem weight preamble).
// ---------------------------------------------------------------
__global__ __launch_bounds__(128) void k3_out_bp(
    const float* __restrict__ out_w, const float* __restrict__ out_b,
    const float* __restrict__ bw1,   const float* __restrict__ bb1,
    const float* __restrict__ bw2,   const float* __restrict__ bb2)
{
    __shared__ float Wo[EE * EE];
    __shared__ float W1t[EE][32];
    __shared__ float ob[EE], b1[32], w2[32];
    __shared__ float b2s;
    for (int i = threadIdx.x; i < EE * EE; i += 128) Wo[i] = out_w[i];
    for (int i = threadIdx.x; i < 32 * EE; i += 128) {
        int m = i / EE, o = i % EE;
        W1t[o][m] = bw1[i];
    }
    for (int i = threadIdx.x; i < EE; i += 128) ob[i] = out_b[i];
    if (threadIdx.x < 32) { b1[threadIdx.x] = bb1[threadIdx.x]; w2[threadIdx.x] = bw2[threadIdx.x]; }
    if (threadIdx.x == 0) b2s = bb2[0];
    __syncthreads();

#pragma unroll 1
    for (int rr = 0; rr < 2; rr++) {
        int row = blockIdx.x * 256 + rr * 128 + threadIdx.x;

        float c[EE];
        const float4* cp = (const float4*)(g_ctx + (size_t)row * EE);
#pragma unroll
        for (int j = 0; j < 16; j++) {
            float4 v = cp[j];
            c[4*j] = v.x; c[4*j+1] = v.y; c[4*j+2] = v.z; c[4*j+3] = v.w;
        }

        float hid[32];
#pragma unroll
        for (int m = 0; m < 32; m++) hid[m] = b1[m];

        float4* ap = (float4*)(g_attn + (size_t)row * EE);
        for (int o4 = 0; o4 < 16; o4++) {
            float a[4];
#pragma unroll
            for (int u = 0; u < 4; u++) {
                int o = o4 * 4 + u;
                float s = ob[o];
                const float4* wr = (const float4*)(Wo + o * EE);
#pragma unroll
                for (int j = 0; j < 16; j++) {
                    float4 w = wr[j];
                    s += c[4*j]*w.x + c[4*j+1]*w.y + c[4*j+2]*w.z + c[4*j+3]*w.w;
                }
                a[u] = s;
#pragma unroll
                for (int m = 0; m < 32; m++) hid[m] += s * W1t[o][m];
            }
            float4 r = {a[0], a[1], a[2], a[3]};
            ap[o4] = r;
        }

        float z = b2s;
#pragma unroll
        for (int m = 0; m < 32; m++) z += fmaxf(hid[m], 0.f) * w2[m];
        float bs = 1.f / (1.f + __expf(-z));

        int tt = row & (TT - 1);
        g_starts[row] = (tt == 0) || ((tt <= TT - 2) && (bs > 0.2f));
    }
}

// ---------------------------------------------------------------
// k4: segment means. Block = batch, thread = channel. Deterministic
// sequential sweep (segments contiguous in t). Tail rows zeroed.
// ---------------------------------------------------------------
__global__ __launch_bounds__(64) void k4_means()
{
    int b = blockIdx.x;
    int e = threadIdx.x;
    __shared__ int ss[TT];
    for (int i = threadIdx.x; i < TT; i += 64) ss[i] = g_starts[b * TT + i];
    __syncthreads();

    const float* ap = g_attn  + (size_t)b * TT * EE + e;
    float*       mp = g_means + (size_t)b * TT * EE + e;

    float sum = 0.f, cnt = 0.f;
    int seg = -1;
#pragma unroll 8
    for (int t = 0; t < TT; t++) {
        float av = ap[(size_t)t * EE];
        if (ss[t]) {
            if (seg >= 0) mp[(size_t)seg * EE] = sum / cnt;
            seg++; sum = 0.f; cnt = 0.f;
        }
        sum += av;
        cnt += 1.f;
    }
    mp[(size_t)seg * EE] = sum / cnt;
    for (int s = seg + 1; s < TT; s++) mp[(size_t)s * EE] = 0.f;
}

// ---------------------------------------------------------------
// k5: out = padded_means @ proj_w^T + proj_b. TWO rows per thread.
// ---------------------------------------------------------------
__global__ __launch_bounds__(128) void k5_proj(const float* __restrict__ pw,
                                               const float* __restrict__ pb,
                                               float* __restrict__ out)
{
    __shared__ float Pw[EE * EE];
    __shared__ float Pb[EE];
    for (int i = threadIdx.x; i < EE * EE; i += 128) Pw[i] = pw[i];
    for (int i = threadIdx.x; i < EE; i += 128) Pb[i] = pb[i];
    __syncthreads();

#pragma unroll 1
    for (int rr = 0; rr < 2; rr++) {
        int row = blockIdx.x * 256 + rr * 128 + threadIdx.x;
        float m[EE];
        const float4* mp = (const float4*)(g_means + (size_t)row * EE);
#pragma unroll
        for (int j = 0; j < 16; j++) {
            float4 v = mp[j];
            m[4*j] = v.x; m[4*j+1] = v.y; m[4*j+2] = v.z; m[4*j+3] = v.w;
        }

        float4* op = (float4*)(out + (size_t)row * EE);
        for (int o4 = 0; o4 < 16; o4++) {
            float a[4];
#pragma unroll
            for (int u = 0; u < 4; u++) {
                int o = o4 * 4 + u;
                float s = Pb[o];
                const float4* wr = (const float4*)(Pw + o * EE);
#pragma unroll
                for (int j = 0; j < 16; j++) {
                    float4 w = wr[j];
                    s += m[4*j]*w.x + m[4*j+1]*w.y + m[4*j+2]*w.z + m[4*j+3]*w.w;
                }
                a[u] = s;
            }
            float4 r = {a[0], a[1], a[2], a[3]};
            op[o4] = r;
        }
    }
}

// ---------------------------------------------------------------
extern "C" void kernel_launch(void* const* d_in, const int* in_sizes, int n_in,
                              void* d_out, int out_size)
{
    const float* x    = (const float*)d_in[0];
    const float* w_in = (const float*)d_in[1];
    const float* b_in = (const float*)d_in[2];
    const float* ipw  = (const float*)d_in[3];
    const float* ipb  = (const float*)d_in[4];
    const float* ow   = (const float*)d_in[5];
    const float* obv  = (const float*)d_in[6];
    const float* b1w  = (const float*)d_in[7];
    const float* b1b  = (const float*)d_in[8];
    const float* b2w  = (const float*)d_in[9];
    const float* b2b  = (const float*)d_in[10];
    const float* pw   = (const float*)d_in[11];
    const float* pb   = (const float*)d_in[12];
    float* out = (float*)d_out;

    k0_fold<<<1, QKV3>>>(w_in, b_in, ipw, ipb);
    k1_qkv<<<ROWS / 128, 128>>>(x);
    k2_attn<<<BB * HH * 8, 128>>>();
    k3_out_bp<<<ROWS / 256, 128>>>(ow, obv, b1w, b1b, b2w, b2b);
    k4_means<<<BB, 64>>>();
    k5_proj<<<ROWS / 256, 128>>>(pw, pb, out);
}

// round 11
// speedup vs baseline: 2.0794x; 1.1369x over previous
#include <cuda_runtime.h>
#include <cuda_bf16.h>
#include <cstdint>

#define BB   64
#define TT   1024
#define IND  7
#define EE   64
#define HH   2
#define DHH  32
#define QKV3 192
#define ROWS (BB*TT)

#define ATTN_SCALE 0.17677669529663687f  // 1/sqrt(32)

// cp.async 16B: global -> shared
#define CP_ASYNC16(dst_u32, src_ptr) \
    asm volatile("cp.async.cg.shared.global [%0], [%1], 16;" :: "r"(dst_u32), "l"(src_ptr) : "memory")
#define CP_COMMIT()   asm volatile("cp.async.commit_group;" ::: "memory")
#define CP_WAIT(N)    asm volatile("cp.async.wait_group %0;" :: "n"(N) : "memory")

// pack two f32 into bf16x2 (lo = low half in memory order)
#define PACK_BF2(u, hi, lo) \
    asm("cvt.rn.bf16x2.f32 %0, %1, %2;" : "=r"(u) : "f"(hi), "f"(lo))

// m16n8k16 bf16 MMA, D += A*B (C==D registers)
#define MMAB16(d, a, b) \
    asm volatile("mma.sync.aligned.m16n8k16.row.col.f32.bf16.bf16.f32 " \
        "{%0,%1,%2,%3}, {%4,%5,%6,%7}, {%8,%9}, {%0,%1,%2,%3};" \
        : "+f"((d)[0]), "+f"((d)[1]), "+f"((d)[2]), "+f"((d)[3]) \
        : "r"((a)[0]), "r"((a)[1]), "r"((a)[2]), "r"((a)[3]), "r"((b)[0]), "r"((b)[1]))

// ---------- scratch (device globals; no allocation allowed) ----------
__device__ float    g_wc[QKV3 * IND];          // folded qkv weight [192,7]
__device__ float    g_bc[QKV3];                // folded qkv bias
__device__ uint32_t g_qk[(size_t)ROWS * 64];   // [row][128 bf16]: Q dims 0..63, K dims 64..127
__device__ __nv_bfloat16 g_vt[(size_t)BB * HH * DHH * TT]; // V^T [b,h][dh][T], bf16
__device__ float    g_ctx[(size_t)ROWS * EE];  // [B*T, 64]
__device__ float    g_attn[(size_t)ROWS * EE]; // attn_out [B*T, 64]
__device__ int      g_starts[ROWS];            // boundary flags [B*T]
__device__ float    g_means[(size_t)ROWS * EE];// padded segment means [B*T, 64]

// ---------------------------------------------------------------
// k0: fold input projection into the qkv projection.
// ---------------------------------------------------------------
__global__ void k0_fold(const float* __restrict__ w_in, const float* __restrict__ b_in,
                        const float* __restrict__ W, const float* __restrict__ bqkv)
{
    int o = threadIdx.x;           // 0..191
    if (o >= QKV3) return;
    float wc[IND];
#pragma unroll
    for (int i = 0; i < IND; i++) wc[i] = 0.f;
    float bc = bqkv[o];
    for (int j = 0; j < EE; j++) {
        float wj = W[o * EE + j];
        bc += wj * b_in[j];
#pragma unroll
        for (int i = 0; i < IND; i++) wc[i] += wj * w_in[j * IND + i];
    }
#pragma unroll
    for (int i = 0; i < IND; i++) g_wc[o * IND + i] = wc[i];
    g_bc[o] = bc;
}

// ---------------------------------------------------------------
// k1: qkv rows from x (192x7 folded GEMM). One row per thread.
// Q,K -> bf16 pairs in g_qk [row][64 u32]; V -> bf16 transposed g_vt.
// ---------------------------------------------------------------
__global__ __launch_bounds__(128) void k1_qkv(const float* __restrict__ x)
{
    __shared__ float Wc[QKV3 * IND];
    __shared__ float bc[QKV3];
    for (int i = threadIdx.x; i < QKV3 * IND; i += 128) Wc[i] = g_wc[i];
    for (int i = threadIdx.x; i < QKV3; i += 128)       bc[i] = g_bc[i];
    __syncthreads();

    int row = blockIdx.x * 128 + threadIdx.x;
    int b_  = row >> 10;
    int t_  = row & (TT - 1);

    float xr[IND];
#pragma unroll
    for (int i = 0; i < IND; i++) xr[i] = x[(size_t)row * IND + i];

    uint32_t* dst = g_qk + (size_t)row * 64;
    for (int o4 = 0; o4 < 48; o4++) {
        float a[4];
#pragma unroll
        for (int u = 0; u < 4; u++) {
            int o = o4 * 4 + u;
            float s = bc[o];
#pragma unroll
            for (int i = 0; i < IND; i++) s += xr[i] * Wc[o * IND + i];
            a[u] = s;
        }
        if (o4 < 32) {                 // Q (o4<16) and K (16<=o4<32)
            uint32_t u01, u23;
            PACK_BF2(u01, a[1], a[0]);
            PACK_BF2(u23, a[3], a[2]);
            dst[o4 * 2]     = u01;
            dst[o4 * 2 + 1] = u23;
        } else {                       // V -> transposed bf16
#pragma unroll
            for (int u = 0; u < 4; u++) {
                int o = o4 * 4 + u;
                int h = (o - 128) >> 5;
                int d = (o - 128) & 31;
                g_vt[((size_t)((b_ * HH + h) * DHH + d)) * TT + t_] = __float2bfloat16(a[u]);
            }
        }
    }
}

// ---------------------------------------------------------------
// k2: bf16 tensor-core flash attention (mma.sync m16n8k16).
// Block = (b, h, q-tile of 128). 4 warps, warp = 32 queries (2 m16 tiles).
// Keys in 64-key chunks, DOUBLE-BUFFERED via cp.async (chunk kc+1 issued
// before chunk kc compute). Per 16-key group: S via 2 n8-tiles (4 MMA),
// fp32 exp, P packed to bf16x2 is DIRECTLY the k16 A-fragment (C cols
// {2t,2t+1} == A half-pairs; hi keys = 2nd S tile) -> no permutation.
// PV: 4 MMA over dh=32. fp32 denominators + normalize. Scores tiny ->
// exp without max-subtraction is exact softmax.
// smem strides: K rows 80B, Vt rows 144B -> conflict-free frag LDS.
// ---------------------------------------------------------------
__global__ __launch_bounds__(128) void k2_attn()
{
    int qt = blockIdx.x & 7;
    int h  = (blockIdx.x >> 3) & 1;
    int b  = blockIdx.x >> 4;

    // per buffer: K 64 rows x 80B = 1280 u32 ; Vt 32 rows x 144B = 1152 u32
    __shared__ uint32_t sbuf[2][2432];
    const uint32_t s_base = (uint32_t)__cvta_generic_to_shared(&sbuf[0][0]);

    int tid  = threadIdx.x;
    int w    = tid >> 5;
    int lane = tid & 31;
    int g    = lane >> 2;     // 0..7
    int t    = lane & 3;      // 0..3
    int qb   = qt * 128 + w * 32;

    // ---- Q A-fragments: A[m][ks][4], bf16x2 pairs ----
    uint32_t A[2][2][4];
#pragma unroll
    for (int m = 0; m < 2; m++) {
        const uint32_t* q0 = g_qk + (size_t)(b * TT + qb + m * 16 + g) * 64;
        const uint32_t* q1 = q0 + 8 * 64;
#pragma unroll
        for (int ks = 0; ks < 2; ks++) {
            int j = h * 16 + ks * 8 + t;
            A[m][ks][0] = q0[j];
            A[m][ks][1] = q1[j];
            A[m][ks][2] = q0[j + 4];
            A[m][ks][3] = q1[j + 4];
        }
    }

    float ctx[2][4][4];
#pragma unroll
    for (int m = 0; m < 2; m++)
#pragma unroll
        for (int n = 0; n < 4; n++)
#pragma unroll
            for (int u = 0; u < 4; u++) ctx[m][n][u] = 0.f;
    float ds[2][2] = {{0.f, 0.f}, {0.f, 0.f}};

    // issue async copy of 64-key chunk kc into buffer `buf`
    auto issue_copy = [&](int kc, int buf) {
        uint32_t kdst = s_base + (uint32_t)buf * 9728u;
        const char* ksrc = (const char*)g_qk + (size_t)(b * TT + kc * 64) * 256 + 128 + h * 64;
#pragma unroll
        for (int it = 0; it < 2; it++) {
            int l = it * 128 + tid;         // 256: 64 rows x 4 segs
            int r = l >> 2, seg = l & 3;
            CP_ASYNC16(kdst + (uint32_t)r * 80u + (uint32_t)seg * 16u,
                       ksrc + (size_t)r * 256 + seg * 16);
        }
        uint32_t vdst = s_base + (uint32_t)buf * 9728u + 5120u;
        const char* vsrc = (const char*)g_vt + (size_t)(b * HH + h) * DHH * 2048 + (size_t)kc * 128;
#pragma unroll
        for (int it = 0; it < 2; it++) {
            int l = it * 128 + tid;         // 256: 32 rows x 8 segs
            int dh = l >> 3, q8 = l & 7;
            CP_ASYNC16(vdst + (uint32_t)dh * 144u + (uint32_t)q8 * 16u,
                       vsrc + (size_t)dh * 2048 + q8 * 16);
        }
        CP_COMMIT();
    };

    issue_copy(0, 0);

#pragma unroll 1
    for (int kc = 0; kc < 16; kc++) {
        int cur = kc & 1;
        if (kc < 15) {
            issue_copy(kc + 1, cur ^ 1);   // overlap next copy with this compute
            CP_WAIT(1);
        } else {
            CP_WAIT(0);
        }
        __syncthreads();

        const uint32_t* kb_s = sbuf[cur];          // K: row stride 20 u32
        const uint32_t* vb_s = sbuf[cur] + 1280;   // V: row stride 36 u32

#pragma unroll
        for (int grp = 0; grp < 4; grp++) {        // 16 keys each
            // QK B-frags: b_qk[ks][nt]: keys nt*8+g (within group)
            uint32_t b_qk[2][2][2];
#pragma unroll
            for (int nt = 0; nt < 2; nt++) {
                int keyl = grp * 16 + nt * 8 + g;
#pragma unroll
                for (int ks = 0; ks < 2; ks++) {
                    b_qk[ks][nt][0] = kb_s[keyl * 20 + ks * 8 + t];
                    b_qk[ks][nt][1] = kb_s[keyl * 20 + ks * 8 + t + 4];
                }
            }
            // V B-frags: b_v[nt]: dh nt*8+g, keys grp*16 + {2t,2t+1,2t+8,2t+9}
            uint32_t b_v[4][2];
#pragma unroll
            for (int nt = 0; nt < 4; nt++) {
                int r = (nt * 8 + g) * 36 + grp * 8 + t;
                b_v[nt][0] = vb_s[r];
                b_v[nt][1] = vb_s[r + 4];
            }
#pragma unroll
            for (int m = 0; m < 2; m++) {
                float clo[4] = {0.f, 0.f, 0.f, 0.f};
                float chi[4] = {0.f, 0.f, 0.f, 0.f};
                MMAB16(clo, A[m][0], b_qk[0][0]);
                MMAB16(clo, A[m][1], b_qk[1][0]);
                MMAB16(chi, A[m][0], b_qk[0][1]);
                MMAB16(chi, A[m][1], b_qk[1][1]);

                float pl0 = __expf(clo[0] * ATTN_SCALE);
                float pl1 = __expf(clo[1] * ATTN_SCALE);
                float pl2 = __expf(clo[2] * ATTN_SCALE);
                float pl3 = __expf(clo[3] * ATTN_SCALE);
                float ph0 = __expf(chi[0] * ATTN_SCALE);
                float ph1 = __expf(chi[1] * ATTN_SCALE);
                float ph2 = __expf(chi[2] * ATTN_SCALE);
                float ph3 = __expf(chi[3] * ATTN_SCALE);

                ds[m][0] += (pl0 + pl1) + (ph0 + ph1);   // row g
                ds[m][1] += (pl2 + pl3) + (ph2 + ph3);   // row g+8

                uint32_t pa[4];
                PACK_BF2(pa[0], pl1, pl0);   // row g,  keys 2t,2t+1
                PACK_BF2(pa[1], pl3, pl2);   // row g+8, keys 2t,2t+1
                PACK_BF2(pa[2], ph1, ph0);   // row g,  keys 2t+8,2t+9
                PACK_BF2(pa[3], ph3, ph2);   // row g+8, keys 2t+8,2t+9

                MMAB16(ctx[m][0], pa, b_v[0]);
                MMAB16(ctx[m][1], pa, b_v[1]);
                MMAB16(ctx[m][2], pa, b_v[2]);
                MMAB16(ctx[m][3], pa, b_v[3]);
            }
        }
        __syncthreads();
    }

    // ---- reduce denominators across the quad ----
#pragma unroll
    for (int m = 0; m < 2; m++)
#pragma unroll
        for (int i = 0; i < 2; i++) {
            ds[m][i] += __shfl_xor_sync(0xffffffffu, ds[m][i], 1);
            ds[m][i] += __shfl_xor_sync(0xffffffffu, ds[m][i], 2);
        }

    // ---- normalize + write ctx (fp32) ----
#pragma unroll
    for (int m = 0; m < 2; m++) {
        float inv0 = 1.f / ds[m][0];
        float inv1 = 1.f / ds[m][1];
        int r0 = b * TT + qb + m * 16 + g;
        float* o0 = g_ctx + (size_t)r0 * EE + h * DHH;
        float* o1 = o0 + 8 * EE;
#pragma unroll
        for (int n = 0; n < 4; n++) {
            float2 lo = {ctx[m][n][0] * inv0, ctx[m][n][1] * inv0};
            float2 hi = {ctx[m][n][2] * inv1, ctx[m][n][3] * inv1};
            *(float2*)(o0 + n * 8 + 2 * t) = lo;
            *(float2*)(o1 + n * 8 + 2 * t) = hi;
        }
    }
}

// ---------------------------------------------------------------
// k3: attn_out = ctx @ out_w^T + out_b, fused with the boundary MLP.
// FOUR rows per thread, sequential (amortizes the 25KB smem weight
// preamble; measured t(n) ~ 43 + 24/n us from the 1-row/2-row points).
// ---------------------------------------------------------------
__global__ __launch_bounds__(128) void k3_out_bp(
    const float* __restrict__ out_w, const float* __restrict__ out_b,
    const float* __restrict__ bw1,   const float* __restrict__ bb1,
    const float* __restrict__ bw2,   const float* __restrict__ bb2)
{
    __shared__ float Wo[EE * EE];
    __shared__ float W1t[EE][32];
    __shared__ float ob[EE], b1[32], w2[32];
    __shared__ float b2s;
    for (int i = threadIdx.x; i < EE * EE; i += 128) Wo[i] = out_w[i];
    for (int i = threadIdx.x; i < 32 * EE; i += 128) {
        int m = i / EE, o = i % EE;
        W1t[o][m] = bw1[i];
    }
    for (int i = threadIdx.x; i < EE; i += 128) ob[i] = out_b[i];
    if (threadIdx.x < 32) { b1[threadIdx.x] = bb1[threadIdx.x]; w2[threadIdx.x] = bw2[threadIdx.x]; }
    if (threadIdx.x == 0) b2s = bb2[0];
    __syncthreads();

#pragma unroll 1
    for (int rr = 0; rr < 4; rr++) {
        int row = blockIdx.x * 512 + rr * 128 + threadIdx.x;

        float c[EE];
        const float4* cp = (const float4*)(g_ctx + (size_t)row * EE);
#pragma unroll
        for (int j = 0; j < 16; j++) {
            float4 v = cp[j];
            c[4*j] = v.x; c[4*j+1] = v.y; c[4*j+2] = v.z; c[4*j+3] = v.w;
        }

        float hid[32];
#pragma unroll
        for (int m = 0; m < 32; m++) hid[m] = b1[m];

        float4* ap = (float4*)(g_attn + (size_t)row * EE);
        for (int o4 = 0; o4 < 16; o4++) {
            float a[4];
#pragma unroll
            for (int u = 0; u < 4; u++) {
                int o = o4 * 4 + u;
                float s = ob[o];
                const float4* wr = (const float4*)(Wo + o * EE);
#pragma unroll
                for (int j = 0; j < 16; j++) {
                    float4 w = wr[j];
                    s += c[4*j]*w.x + c[4*j+1]*w.y + c[4*j+2]*w.z + c[4*j+3]*w.w;
                }
                a[u] = s;
#pragma unroll
                for (int m = 0; m < 32; m++) hid[m] += s * W1t[o][m];
            }
            float4 r = {a[0], a[1], a[2], a[3]};
            ap[o4] = r;
        }

        float z = b2s;
#pragma unroll
        for (int m = 0; m < 32; m++) z += fmaxf(hid[m], 0.f) * w2[m];
        float bs = 1.f / (1.f + __expf(-z));

        int tt = row & (TT - 1);
        g_starts[row] = (tt == 0) || ((tt <= TT - 2) && (bs > 0.2f));
    }
}

// ---------------------------------------------------------------
// k4: segment means. Block = batch, thread = channel. Deterministic
// sequential sweep (segments contiguous in t). Tail rows zeroed.
// ---------------------------------------------------------------
__global__ __launch_bounds__(64) void k4_means()
{
    int b = blockIdx.x;
    int e = threadIdx.x;
    __shared__ int ss[TT];
    for (int i = threadIdx.x; i < TT; i += 64) ss[i] = g_starts[b * TT + i];
    __syncthreads();

    const float* ap = g_attn  + (size_t)b * TT * EE + e;
    float*       mp = g_means + (size_t)b * TT * EE + e;

    float sum = 0.f, cnt = 0.f;
    int seg = -1;
#pragma unroll 8
    for (int t = 0; t < TT; t++) {
        float av = ap[(size_t)t * EE];
        if (ss[t]) {
            if (seg >= 0) mp[(size_t)seg * EE] = sum / cnt;
            seg++; sum = 0.f; cnt = 0.f;
        }
        sum += av;
        cnt += 1.f;
    }
    mp[(size_t)seg * EE] = sum / cnt;
    for (int s = seg + 1; s < TT; s++) mp[(size_t)s * EE] = 0.f;
}

// ---------------------------------------------------------------
// k5: out = padded_means @ proj_w^T + proj_b. FOUR rows per thread
// (sequential), amortizing the 16KB weight preamble like k3.
// ---------------------------------------------------------------
__global__ __launch_bounds__(128) void k5_proj(const float* __restrict__ pw,
                                               const float* __restrict__ pb,
                                               float* __restrict__ out)
{
    __shared__ float Pw[EE * EE];
    __shared__ float Pb[EE];
    for (int i = threadIdx.x; i < EE * EE; i += 128) Pw[i] = pw[i];
    for (int i = threadIdx.x; i < EE; i += 128) Pb[i] = pb[i];
    __syncthreads();

#pragma unroll 1
    for (int rr = 0; rr < 4; rr++) {
        int row = blockIdx.x * 512 + rr * 128 + threadIdx.x;
        float m[EE];
        const float4* mp = (const float4*)(g_means + (size_t)row * EE);
#pragma unroll
        for (int j = 0; j < 16; j++) {
            float4 v = mp[j];
            m[4*j] = v.x; m[4*j+1] = v.y; m[4*j+2] = v.z; m[4*j+3] = v.w;
        }

        float4* op = (float4*)(out + (size_t)row * EE);
        for (int o4 = 0; o4 < 16; o4++) {
            float a[4];
#pragma unroll
            for (int u = 0; u < 4; u++) {
                int o = o4 * 4 + u;
                float s = Pb[o];
                const float4* wr = (const float4*)(Pw + o * EE);
#pragma unroll
                for (int j = 0; j < 16; j++) {
                    float4 w = wr[j];
                    s += m[4*j]*w.x + m[4*j+1]*w.y + m[4*j+2]*w.z + m[4*j+3]*w.w;
                }
                a[u] = s;
            }
            float4 r = {a[0], a[1], a[2], a[3]};
            op[o4] = r;
        }
    }
}

// ---------------------------------------------------------------
extern "C" void kernel_launch(void* const* d_in, const int* in_sizes, int n_in,
                              void* d_out, int out_size)
{
    const float* x    = (const float*)d_in[0];
    const float* w_in = (const float*)d_in[1];
    const float* b_in = (const float*)d_in[2];
    const float* ipw  = (const float*)d_in[3];
    const float* ipb  = (const float*)d_in[4];
    const float* ow   = (const float*)d_in[5];
    const float* obv  = (const float*)d_in[6];
    const float* b1w  = (const float*)d_in[7];
    const float* b1b  = (const float*)d_in[8];
    const float* b2w  = (const float*)d_in[9];
    const float* b2b  = (const float*)d_in[10];
    const float* pw   = (const float*)d_in[11];
    const float* pb   = (const float*)d_in[12];
    float* out = (float*)d_out;

    k0_fold<<<1, QKV3>>>(w_in, b_in, ipw, ipb);
    k1_qkv<<<ROWS / 128, 128>>>(x);
    k2_attn<<<BB * HH * 8, 128>>>();
    k3_out_bp<<<ROWS / 512, 128>>>(ow, obv, b1w, b1b, b2w, b2b);
    k4_means<<<BB, 64>>>();
    k5_proj<<<ROWS / 512, 128>>>(pw, pb, out);
}